// round 1
// baseline (speedup 1.0000x reference)
#include <cuda_runtime.h>
#include <math.h>

#define L 16384
#define D 1024
#define A 1024

#define BM 128
#define BN 64
#define BK 16

typedef unsigned long long u64;

// Device scratch (no allocations allowed)
__device__ float g_c[A];       // c = W2 @ h_t + b
__device__ float g_beta[L];    // attention logits
__device__ float g_max;
__device__ float g_sumexp;

__device__ __forceinline__ void ffma2(u64 &d, u64 a, u64 b) {
    // packed 2x fp32 FMA (Blackwell FFMA2) — d.lo += a.lo*b.lo ; d.hi += a.hi*b.hi
    asm("fma.rn.f32x2 %0, %1, %2, %0;" : "+l"(d) : "l"(a), "l"(b));
}

// ---------------------------------------------------------------------------
// K0: zero beta accumulator and output
// ---------------------------------------------------------------------------
__global__ void k_init(float* __restrict__ out) {
    int i = blockIdx.x * blockDim.x + threadIdx.x;
    if (i < L) g_beta[i] = 0.0f;
    if (i < D) out[i] = 0.0f;
}

// ---------------------------------------------------------------------------
// K1: c[a] = dot(W_att[a, D:2D], h_t) + b_att[a]
// ---------------------------------------------------------------------------
__global__ void k_ctx(const float* __restrict__ W, const float* __restrict__ ht,
                      const float* __restrict__ b) {
    int a = blockIdx.x;
    const float* w = W + (size_t)a * (2 * D) + D;
    float s = 0.0f;
    for (int k = threadIdx.x; k < D; k += 256) s = fmaf(w[k], ht[k], s);
    __shared__ float red[8];
    #pragma unroll
    for (int o = 16; o > 0; o >>= 1) s += __shfl_down_sync(0xffffffffu, s, o);
    if ((threadIdx.x & 31) == 0) red[threadIdx.x >> 5] = s;
    __syncthreads();
    if (threadIdx.x == 0) {
        float t = 0.0f;
        #pragma unroll
        for (int i = 0; i < 8; i++) t += red[i];
        g_c[a] = t + b[a];
    }
}

// ---------------------------------------------------------------------------
// K2: fused GEMM + tanh + dot-u epilogue.
//   For tile [l0:l0+128] x [a0:a0+64]:
//     y = h_i_tile @ W1_tile^T          (K = 1024 fully inside this CTA)
//     beta[l] += sum_a tanh(y + c[a]) * u[a]   (atomicAdd partial over a-tiles)
//   Inner loop uses packed f32x2 FMAs: A rows packed in pairs, B duplicated.
// ---------------------------------------------------------------------------
__global__ void __launch_bounds__(256) k_gemm(const float* __restrict__ h_i,
                                              const float* __restrict__ W,
                                              const float* __restrict__ u) {
    __shared__ __align__(16) float sm[BK * BM + BK * (2 * BN)];  // 16 KB
    float (*As)[BM]  = (float (*)[BM])sm;                 // [16][128]
    float (*Bs2)[2 * BN] = (float (*)[2 * BN])(sm + BK * BM); // [16][128], duplicated pairs

    const int tid = threadIdx.x;
    const int tx = tid & 15;   // 0..15 -> 4 A-columns each
    const int ty = tid >> 4;   // 0..15 -> 8 rows each (4 packed pairs)
    const int l0 = blockIdx.x * BM;
    const int a0 = blockIdx.y * BN;

    u64 acc2[4][4];
    #pragma unroll
    for (int p = 0; p < 4; p++)
        #pragma unroll
        for (int j = 0; j < 4; j++) acc2[p][j] = 0ull;

    for (int k0 = 0; k0 < D; k0 += BK) {
        // ---- load A tile: 128x16 floats = 512 float4, 2 per thread ----
        {
            int f = tid;                 // float4 index 0..255
            int r = f >> 2, c4 = f & 3;
            float4 v = *(const float4*)(h_i + (size_t)(l0 + r) * D + k0 + c4 * 4);
            As[c4 * 4 + 0][r] = v.x; As[c4 * 4 + 1][r] = v.y;
            As[c4 * 4 + 2][r] = v.z; As[c4 * 4 + 3][r] = v.w;
            f = tid + 256;
            r = f >> 2; c4 = f & 3;
            float4 w2 = *(const float4*)(h_i + (size_t)(l0 + r) * D + k0 + c4 * 4);
            As[c4 * 4 + 0][r] = w2.x; As[c4 * 4 + 1][r] = w2.y;
            As[c4 * 4 + 2][r] = w2.z; As[c4 * 4 + 3][r] = w2.w;
        }
        // ---- load B tile (W1 rows a0..a0+63, cols k0..k0+15), duplicated ----
        {
            int r = tid >> 2, c4 = tid & 3;
            float4 v = *(const float4*)(W + (size_t)(a0 + r) * (2 * D) + k0 + c4 * 4);
            float vals[4] = {v.x, v.y, v.z, v.w};
            #pragma unroll
            for (int m = 0; m < 4; m++) {
                int kk = c4 * 4 + m;
                Bs2[kk][2 * r + 0] = vals[m];
                Bs2[kk][2 * r + 1] = vals[m];
            }
        }
        __syncthreads();

        #pragma unroll
        for (int kk = 0; kk < BK; kk++) {
            ulonglong2 a01 = *(const ulonglong2*)&As[kk][ty * 8];
            ulonglong2 a23 = *(const ulonglong2*)&As[kk][ty * 8 + 4];
            ulonglong2 b01 = *(const ulonglong2*)&Bs2[kk][tx * 8];
            ulonglong2 b23 = *(const ulonglong2*)&Bs2[kk][tx * 8 + 4];
            u64 ap[4] = {a01.x, a01.y, a23.x, a23.y};
            u64 bp[4] = {b01.x, b01.y, b23.x, b23.y};
            #pragma unroll
            for (int p = 0; p < 4; p++)
                #pragma unroll
                for (int j = 0; j < 4; j++)
                    ffma2(acc2[p][j], ap[p], bp[j]);
        }
        __syncthreads();
    }

    // ---- epilogue: tanh + dot with u, reduce across the 16 tx lanes ----
    float cl[4], ul[4];
    #pragma unroll
    for (int j = 0; j < 4; j++) {
        cl[j] = g_c[a0 + tx * 4 + j];
        ul[j] = u[a0 + tx * 4 + j];
    }

    float (*red)[16] = (float (*)[16])sm;  // reuse smem (synced above)
    #pragma unroll
    for (int p = 0; p < 4; p++) {
        float plo = 0.0f, phi = 0.0f;
        #pragma unroll
        for (int j = 0; j < 4; j++) {
            u64 x = acc2[p][j];
            float lo = __uint_as_float((unsigned)(x & 0xffffffffull));
            float hi = __uint_as_float((unsigned)(x >> 32));
            plo = fmaf(tanhf(lo + cl[j]), ul[j], plo);
            phi = fmaf(tanhf(hi + cl[j]), ul[j], phi);
        }
        red[ty * 8 + 2 * p + 0][tx] = plo;
        red[ty * 8 + 2 * p + 1][tx] = phi;
    }
    __syncthreads();

    if (tid < BM) {
        float s = 0.0f;
        #pragma unroll
        for (int t = 0; t < 16; t++) s += red[tid][t];
        atomicAdd(&g_beta[l0 + tid], s);
    }
}

// ---------------------------------------------------------------------------
// K3: softmax stats over beta[L] (single block)
// ---------------------------------------------------------------------------
__global__ void k_softmax_stats() {
    __shared__ float red[1024];
    int tid = threadIdx.x;
    float m = -1e30f;
    for (int i = tid; i < L; i += 1024) m = fmaxf(m, g_beta[i]);
    red[tid] = m;
    __syncthreads();
    for (int s = 512; s > 0; s >>= 1) {
        if (tid < s) red[tid] = fmaxf(red[tid], red[tid + s]);
        __syncthreads();
    }
    float mx = red[0];
    __syncthreads();
    float sum = 0.0f;
    for (int i = tid; i < L; i += 1024) sum += expf(g_beta[i] - mx);
    red[tid] = sum;
    __syncthreads();
    for (int s = 512; s > 0; s >>= 1) {
        if (tid < s) red[tid] += red[tid + s];
        __syncthreads();
    }
    if (tid == 0) {
        g_max = mx;
        g_sumexp = red[0];
    }
}

// ---------------------------------------------------------------------------
// K4: s[d] = sum_l softmax(beta)_l * h_i[l][d]   (128 rows per block)
// ---------------------------------------------------------------------------
#define OROWS 128
__global__ void __launch_bounds__(256) k_out(const float* __restrict__ h_i,
                                             float* __restrict__ out) {
    __shared__ float w[OROWS];
    int l0 = blockIdx.x * OROWS;
    int tid = threadIdx.x;
    float mx = g_max, se = g_sumexp;
    if (tid < OROWS) w[tid] = expf(g_beta[l0 + tid] - mx) / se;
    __syncthreads();
    float acc[4] = {0.0f, 0.0f, 0.0f, 0.0f};
    for (int l = 0; l < OROWS; l++) {
        float wl = w[l];
        const float* row = h_i + (size_t)(l0 + l) * D;
        #pragma unroll
        for (int j = 0; j < 4; j++)
            acc[j] = fmaf(wl, row[tid + j * 256], acc[j]);
    }
    #pragma unroll
    for (int j = 0; j < 4; j++) atomicAdd(&out[tid + j * 256], acc[j]);
}

// ---------------------------------------------------------------------------
extern "C" void kernel_launch(void* const* d_in, const int* in_sizes, int n_in,
                              void* d_out, int out_size) {
    const float* h_i = (const float*)d_in[0];
    const float* h_t = (const float*)d_in[1];
    const float* W   = (const float*)d_in[2];
    const float* b   = (const float*)d_in[3];
    const float* u   = (const float*)d_in[4];
    float* out = (float*)d_out;

    k_init<<<(L + 255) / 256, 256>>>(out);
    k_ctx<<<A, 256>>>(W, h_t, b);
    dim3 g2(L / BM, A / BN);
    k_gemm<<<g2, 256>>>(h_i, W, u);
    k_softmax_stats<<<1, 1024>>>();
    k_out<<<L / OROWS, 256>>>(h_i, out);
}

// round 3
// speedup vs baseline: 3.8545x; 3.8545x over previous
#include <cuda_runtime.h>
#include <cuda_bf16.h>
#include <math.h>
#include <stdint.h>

#define L 16384
#define D 1024
#define ADIM 1024

#define BM 128
#define BN 128
#define BK 32
#define NCHUNK (D / BK)            // 32

#define SSTR 40                     // smem row stride in bf16 (80 B) — conflict-free ldmatrix
#define TILEB (128 * SSTR * 2)      // 10240 B per 128x32 tile
#define OFF_AH 0
#define OFF_AL (TILEB)
#define OFF_BH (2 * TILEB)
#define OFF_BL (3 * TILEB)
#define STAGE  (4 * TILEB)          // 40960
#define SMEM_TOTAL (2 * STAGE)      // 81920

// ---------------------------------------------------------------------------
// Device scratch (module-load allocated; no runtime allocs)
// ---------------------------------------------------------------------------
__device__ __nv_bfloat16 g_hA[(size_t)L * D];    // h_i hi (natural [L][D])
__device__ __nv_bfloat16 g_lA[(size_t)L * D];    // h_i lo
__device__ __nv_bfloat16 g_hB[(size_t)ADIM * D]; // W1 hi  ([A][D])
__device__ __nv_bfloat16 g_lB[(size_t)ADIM * D]; // W1 lo
__device__ float g_c[ADIM];
__device__ float g_beta[L];
__device__ unsigned g_maxbits;
__device__ float g_sumexp;

// ---------------------------------------------------------------------------
// helpers
// ---------------------------------------------------------------------------
__device__ __forceinline__ uint32_t smem_u32(const void* p) {
    uint32_t a;
    asm("{ .reg .u64 t; cvta.to.shared.u64 t, %1; cvt.u32.u64 %0, t; }" : "=r"(a) : "l"(p));
    return a;
}
__device__ __forceinline__ void ldm4(uint32_t* r, uint32_t addr) {
    asm volatile("ldmatrix.sync.aligned.m8n8.x4.shared.b16 {%0,%1,%2,%3}, [%4];"
                 : "=r"(r[0]), "=r"(r[1]), "=r"(r[2]), "=r"(r[3]) : "r"(addr));
}
__device__ __forceinline__ void mma16816(float* d, const uint32_t* a, uint32_t b0, uint32_t b1) {
    asm volatile("mma.sync.aligned.m16n8k16.row.col.f32.bf16.bf16.f32 "
                 "{%0,%1,%2,%3}, {%4,%5,%6,%7}, {%8,%9}, {%0,%1,%2,%3};"
                 : "+f"(d[0]), "+f"(d[1]), "+f"(d[2]), "+f"(d[3])
                 : "r"(a[0]), "r"(a[1]), "r"(a[2]), "r"(a[3]), "r"(b0), "r"(b1));
}
// accurate fast tanh: 1 - 2/(exp(2x)+1); ex2/rcp approx err ~2^-22
__device__ __forceinline__ float tanh_fast(float x) {
    float e, r;
    asm("ex2.approx.f32 %0, %1;" : "=f"(e) : "f"(x * 2.88539008177792681f));
    asm("rcp.approx.f32 %0, %1;" : "=f"(r) : "f"(e + 1.0f));
    return fmaf(-2.0f, r, 1.0f);
}
__device__ __forceinline__ unsigned enc_f(float f) {
    unsigned u = __float_as_uint(f);
    return (u & 0x80000000u) ? ~u : (u | 0x80000000u);
}
__device__ __forceinline__ float dec_f(unsigned e) {
    unsigned u = (e & 0x80000000u) ? (e ^ 0x80000000u) : ~e;
    return __uint_as_float(u);
}

// ---------------------------------------------------------------------------
// K0: init accumulators
// ---------------------------------------------------------------------------
__global__ void k_init(float* __restrict__ out) {
    int i = blockIdx.x * blockDim.x + threadIdx.x;
    if (i < L) g_beta[i] = 0.0f;
    if (i < D) out[i] = 0.0f;
    if (i == 0) { g_maxbits = 0u; g_sumexp = 0.0f; }
}

// ---------------------------------------------------------------------------
// K1: c[a] = dot(W_att[a, D:2D], h_t) + b_att[a]
// ---------------------------------------------------------------------------
__global__ void k_ctx(const float* __restrict__ W, const float* __restrict__ ht,
                      const float* __restrict__ b) {
    int a = blockIdx.x;
    const float* w = W + (size_t)a * (2 * D) + D;
    float s = 0.0f;
    for (int k = threadIdx.x; k < D; k += 256) s = fmaf(w[k], ht[k], s);
    __shared__ float red[8];
    #pragma unroll
    for (int o = 16; o > 0; o >>= 1) s += __shfl_down_sync(0xffffffffu, s, o);
    if ((threadIdx.x & 31) == 0) red[threadIdx.x >> 5] = s;
    __syncthreads();
    if (threadIdx.x == 0) {
        float t = 0.0f;
        #pragma unroll
        for (int i = 0; i < 8; i++) t += red[i];
        g_c[a] = t + b[a];
    }
}

// ---------------------------------------------------------------------------
// K2a: h_i -> (hi, lo) bf16, natural layout
// ---------------------------------------------------------------------------
__global__ void __launch_bounds__(256) k_conv_h(const float* __restrict__ h) {
    size_t i = ((size_t)blockIdx.x * 256 + threadIdx.x) * 4;
    float4 v = *(const float4*)(h + i);
    __nv_bfloat16 h0 = __float2bfloat16(v.x), h1 = __float2bfloat16(v.y);
    __nv_bfloat16 h2 = __float2bfloat16(v.z), h3 = __float2bfloat16(v.w);
    ushort4 hp, lp;
    hp.x = __bfloat16_as_ushort(h0); hp.y = __bfloat16_as_ushort(h1);
    hp.z = __bfloat16_as_ushort(h2); hp.w = __bfloat16_as_ushort(h3);
    lp.x = __bfloat16_as_ushort(__float2bfloat16(v.x - __bfloat162float(h0)));
    lp.y = __bfloat16_as_ushort(__float2bfloat16(v.y - __bfloat162float(h1)));
    lp.z = __bfloat16_as_ushort(__float2bfloat16(v.z - __bfloat162float(h2)));
    lp.w = __bfloat16_as_ushort(__float2bfloat16(v.w - __bfloat162float(h3)));
    *(ushort4*)(g_hA + i) = hp;
    *(ushort4*)(g_lA + i) = lp;
}

// ---------------------------------------------------------------------------
// K2b: W1 (first D cols of W_att) -> (hi, lo) bf16
// ---------------------------------------------------------------------------
__global__ void __launch_bounds__(256) k_conv_w(const float* __restrict__ W) {
    int a = blockIdx.x;
    int c = threadIdx.x * 4;
    float4 v = *(const float4*)(W + (size_t)a * (2 * D) + c);
    __nv_bfloat16 h0 = __float2bfloat16(v.x), h1 = __float2bfloat16(v.y);
    __nv_bfloat16 h2 = __float2bfloat16(v.z), h3 = __float2bfloat16(v.w);
    ushort4 hp, lp;
    hp.x = __bfloat16_as_ushort(h0); hp.y = __bfloat16_as_ushort(h1);
    hp.z = __bfloat16_as_ushort(h2); hp.w = __bfloat16_as_ushort(h3);
    lp.x = __bfloat16_as_ushort(__float2bfloat16(v.x - __bfloat162float(h0)));
    lp.y = __bfloat16_as_ushort(__float2bfloat16(v.y - __bfloat162float(h1)));
    lp.z = __bfloat16_as_ushort(__float2bfloat16(v.z - __bfloat162float(h2)));
    lp.w = __bfloat16_as_ushort(__float2bfloat16(v.w - __bfloat162float(h3)));
    size_t o = (size_t)a * D + c;
    *(ushort4*)(g_hB + o) = hp;
    *(ushort4*)(g_lB + o) = lp;
}

// ---------------------------------------------------------------------------
// K3: HMMA GEMM (3-pass bf16 split) + fused tanh/dot-u epilogue
// ---------------------------------------------------------------------------
__global__ void __launch_bounds__(256) k_gemm(const float* __restrict__ u_in) {
    extern __shared__ __align__(128) char smem[];
    const uint32_t sbase = smem_u32(smem);
    const int tid = threadIdx.x;
    const int lane = tid & 31, wid = tid >> 5;
    const int warp_m = wid >> 2, warp_n = wid & 3;
    const int l0 = blockIdx.x * BM, a0 = blockIdx.y * BN;

    // ldmatrix per-lane byte offsets within a tile
    uint32_t aoff[4], boff[2];
    #pragma unroll
    for (int i = 0; i < 4; i++)
        aoff[i] = (uint32_t)((warp_m * 64 + i * 16 + (lane & 15)) * (SSTR * 2)
                             + ((lane >> 4) * 16));
    #pragma unroll
    for (int p = 0; p < 2; p++)
        boff[p] = (uint32_t)((warp_n * 32 + p * 16 + (lane & 7) + ((lane >> 4) & 1) * 8)
                             * (SSTR * 2) + (((lane >> 3) & 1) * 16));

    // global load pointers (uint4 = 8 bf16; 128 uint4 per 1024-col row)
    const int row = tid >> 2, seg = tid & 3;
    const uint4* pAh = (const uint4*)g_hA + (size_t)(l0 + row) * 128 + seg;
    const uint4* pAl = (const uint4*)g_lA + (size_t)(l0 + row) * 128 + seg;
    const uint4* pBh = (const uint4*)g_hB + (size_t)(a0 + row) * 128 + seg;
    const uint4* pBl = (const uint4*)g_lB + (size_t)(a0 + row) * 128 + seg;
    const int rstep = 64 * 128;
    const uint32_t s0 = (uint32_t)(row * (SSTR * 2) + seg * 16);
    const uint32_t s1 = s0 + 64 * (SSTR * 2);

    float acc[4][4][4];
    #pragma unroll
    for (int i = 0; i < 4; i++)
        #pragma unroll
        for (int j = 0; j < 4; j++)
            #pragma unroll
            for (int r = 0; r < 4; r++) acc[i][j][r] = 0.0f;

    // prologue: chunk 0 -> stage 0
    {
        char* st = smem;
        *(uint4*)(st + OFF_AH + s0) = pAh[0]; *(uint4*)(st + OFF_AH + s1) = pAh[rstep];
        *(uint4*)(st + OFF_AL + s0) = pAl[0]; *(uint4*)(st + OFF_AL + s1) = pAl[rstep];
        *(uint4*)(st + OFF_BH + s0) = pBh[0]; *(uint4*)(st + OFF_BH + s1) = pBh[rstep];
        *(uint4*)(st + OFF_BL + s0) = pBl[0]; *(uint4*)(st + OFF_BL + s1) = pBl[rstep];
    }
    __syncthreads();

    for (int kc = 0; kc < NCHUNK; kc++) {
        const int cur = kc & 1;
        uint4 rAh[2], rAl[2], rBh[2], rBl[2];
        if (kc + 1 < NCHUNK) {
            const int o = (kc + 1) * 4;
            rAh[0] = pAh[o]; rAh[1] = pAh[o + rstep];
            rAl[0] = pAl[o]; rAl[1] = pAl[o + rstep];
            rBh[0] = pBh[o]; rBh[1] = pBh[o + rstep];
            rBl[0] = pBl[o]; rBl[1] = pBl[o + rstep];
        }
        // compute on stage cur
        {
            const uint32_t base = sbase + (uint32_t)cur * STAGE;
            #pragma unroll
            for (int ks = 0; ks < 2; ks++) {
                uint32_t ah[4][4], al[4][4], bh[2][4], bl[2][4];
                #pragma unroll
                for (int i = 0; i < 4; i++) ldm4(ah[i], base + OFF_AH + aoff[i] + ks * 32);
                #pragma unroll
                for (int i = 0; i < 4; i++) ldm4(al[i], base + OFF_AL + aoff[i] + ks * 32);
                #pragma unroll
                for (int p = 0; p < 2; p++) ldm4(bh[p], base + OFF_BH + boff[p] + ks * 32);
                #pragma unroll
                for (int p = 0; p < 2; p++) ldm4(bl[p], base + OFF_BL + boff[p] + ks * 32);
                #pragma unroll
                for (int i = 0; i < 4; i++)
                    #pragma unroll
                    for (int j = 0; j < 4; j++) {
                        const int p = j >> 1, q = (j & 1) * 2;
                        mma16816(acc[i][j], ah[i], bh[p][q], bh[p][q + 1]);
                        mma16816(acc[i][j], ah[i], bl[p][q], bl[p][q + 1]);
                        mma16816(acc[i][j], al[i], bh[p][q], bh[p][q + 1]);
                    }
            }
        }
        if (kc + 1 < NCHUNK) {
            char* st = smem + (cur ^ 1) * STAGE;
            *(uint4*)(st + OFF_AH + s0) = rAh[0]; *(uint4*)(st + OFF_AH + s1) = rAh[1];
            *(uint4*)(st + OFF_AL + s0) = rAl[0]; *(uint4*)(st + OFF_AL + s1) = rAl[1];
            *(uint4*)(st + OFF_BH + s0) = rBh[0]; *(uint4*)(st + OFF_BH + s1) = rBh[1];
            *(uint4*)(st + OFF_BL + s0) = rBl[0]; *(uint4*)(st + OFF_BL + s1) = rBl[1];
        }
        __syncthreads();
    }

    // epilogue: beta_l += sum_a tanh(y + c[a]) * u[a]
    const int gID = lane >> 2, tig = lane & 3;
    float cl[4][2], ul[4][2];
    #pragma unroll
    for (int j = 0; j < 4; j++) {
        const int ag = a0 + warp_n * 32 + j * 8 + 2 * tig;
        cl[j][0] = g_c[ag];     cl[j][1] = g_c[ag + 1];
        ul[j][0] = u_in[ag];    ul[j][1] = u_in[ag + 1];
    }
    #pragma unroll
    for (int i = 0; i < 4; i++) {
        float sA = 0.0f, sB = 0.0f;
        #pragma unroll
        for (int j = 0; j < 4; j++) {
            sA = fmaf(tanh_fast(acc[i][j][0] + cl[j][0]), ul[j][0], sA);
            sA = fmaf(tanh_fast(acc[i][j][1] + cl[j][1]), ul[j][1], sA);
            sB = fmaf(tanh_fast(acc[i][j][2] + cl[j][0]), ul[j][0], sB);
            sB = fmaf(tanh_fast(acc[i][j][3] + cl[j][1]), ul[j][1], sB);
        }
        sA += __shfl_xor_sync(0xffffffffu, sA, 1);
        sA += __shfl_xor_sync(0xffffffffu, sA, 2);
        sB += __shfl_xor_sync(0xffffffffu, sB, 1);
        sB += __shfl_xor_sync(0xffffffffu, sB, 2);
        if (tig == 0) {
            const int r = l0 + warp_m * 64 + i * 16 + gID;
            atomicAdd(&g_beta[r], sA);
            atomicAdd(&g_beta[r + 8], sB);
        }
    }
}

// ---------------------------------------------------------------------------
// K4: softmax stats (parallel atomics)
// ---------------------------------------------------------------------------
__global__ void k_max() {
    int i = blockIdx.x * 1024 + threadIdx.x;
    float v = g_beta[i];
    #pragma unroll
    for (int o = 16; o > 0; o >>= 1) v = fmaxf(v, __shfl_xor_sync(0xffffffffu, v, o));
    __shared__ float r[32];
    if ((threadIdx.x & 31) == 0) r[threadIdx.x >> 5] = v;
    __syncthreads();
    if (threadIdx.x < 32) {
        v = r[threadIdx.x];
        #pragma unroll
        for (int o = 16; o > 0; o >>= 1) v = fmaxf(v, __shfl_xor_sync(0xffffffffu, v, o));
        if (threadIdx.x == 0) atomicMax(&g_maxbits, enc_f(v));
    }
}
__global__ void k_sum() {
    int i = blockIdx.x * 1024 + threadIdx.x;
    float mx = dec_f(g_maxbits);
    float v = expf(g_beta[i] - mx);
    #pragma unroll
    for (int o = 16; o > 0; o >>= 1) v += __shfl_xor_sync(0xffffffffu, v, o);
    __shared__ float r[32];
    if ((threadIdx.x & 31) == 0) r[threadIdx.x >> 5] = v;
    __syncthreads();
    if (threadIdx.x < 32) {
        v = r[threadIdx.x];
        #pragma unroll
        for (int o = 16; o > 0; o >>= 1) v += __shfl_xor_sync(0xffffffffu, v, o);
        if (threadIdx.x == 0) atomicAdd(&g_sumexp, v);
    }
}

// ---------------------------------------------------------------------------
// K5: s[d] = sum_l alpha_l * h_i[l][d]
// ---------------------------------------------------------------------------
#define OROWS 128
__global__ void __launch_bounds__(256) k_out(const float* __restrict__ h_i,
                                             float* __restrict__ out) {
    __shared__ float w[OROWS];
    int l0 = blockIdx.x * OROWS;
    int tid = threadIdx.x;
    float mx = dec_f(g_maxbits), se = g_sumexp;
    if (tid < OROWS) w[tid] = expf(g_beta[l0 + tid] - mx) / se;
    __syncthreads();
    float acc[4] = {0.0f, 0.0f, 0.0f, 0.0f};
    for (int l = 0; l < OROWS; l++) {
        float wl = w[l];
        const float* rp = h_i + (size_t)(l0 + l) * D;
        #pragma unroll
        for (int j = 0; j < 4; j++)
            acc[j] = fmaf(wl, rp[tid + j * 256], acc[j]);
    }
    #pragma unroll
    for (int j = 0; j < 4; j++) atomicAdd(&out[tid + j * 256], acc[j]);
}

// ---------------------------------------------------------------------------
extern "C" void kernel_launch(void* const* d_in, const int* in_sizes, int n_in,
                              void* d_out, int out_size) {
    const float* h_i = (const float*)d_in[0];
    const float* h_t = (const float*)d_in[1];
    const float* W   = (const float*)d_in[2];
    const float* b   = (const float*)d_in[3];
    const float* u   = (const float*)d_in[4];
    float* out = (float*)d_out;

    static bool attr_set = false;
    if (!attr_set) {
        cudaFuncSetAttribute(k_gemm, cudaFuncAttributeMaxDynamicSharedMemorySize, SMEM_TOTAL);
        attr_set = true;
    }

    k_init<<<64, 256>>>(out);
    k_ctx<<<ADIM, 256>>>(W, h_t, b);
    k_conv_h<<<(int)(((size_t)L * D) / 1024), 256>>>(h_i);
    k_conv_w<<<ADIM, 256>>>(W);
    dim3 g(L / BM, ADIM / BN);
    k_gemm<<<g, 256, SMEM_TOTAL>>>(u);
    k_max<<<16, 1024>>>();
    k_sum<<<16, 1024>>>();
    k_out<<<L / OROWS, 256>>>(h_i, out);
}

// round 4
// speedup vs baseline: 4.8976x; 1.2706x over previous
#include <cuda_runtime.h>
#include <cuda_bf16.h>
#include <math.h>
#include <stdint.h>

#define L 16384
#define D 1024
#define ADIM 1024

#define BM 128
#define BN 128
#define BK 64
#define NCH (D / BK)               // 16
#define STAGES 3

#define TILEB (BM * BK * 2)        // 16384 B per 128x64 bf16 tile
#define OFF_AH 0
#define OFF_AL (TILEB)
#define OFF_BH (2 * TILEB)
#define OFF_BL (3 * TILEB)
#define STAGEB (4 * TILEB)         // 65536
#define SMEM_TOTAL (STAGES * STAGEB) // 196608

// ---------------------------------------------------------------------------
// Device scratch
// ---------------------------------------------------------------------------
__device__ __nv_bfloat16 g_hA[(size_t)L * D];
__device__ __nv_bfloat16 g_lA[(size_t)L * D];
__device__ __nv_bfloat16 g_hB[(size_t)ADIM * D];
__device__ __nv_bfloat16 g_lB[(size_t)ADIM * D];
__device__ float g_c[ADIM];
__device__ float g_beta[L];
__device__ unsigned g_maxbits;
__device__ float g_sumexp;

// ---------------------------------------------------------------------------
// helpers
// ---------------------------------------------------------------------------
__device__ __forceinline__ uint32_t smem_u32(const void* p) {
    uint32_t a;
    asm("{ .reg .u64 t; cvta.to.shared.u64 t, %1; cvt.u32.u64 %0, t; }" : "=r"(a) : "l"(p));
    return a;
}
__device__ __forceinline__ void cpa16(uint32_t dst, const void* src) {
    asm volatile("cp.async.cg.shared.global [%0], [%1], 16;" :: "r"(dst), "l"(src));
}
__device__ __forceinline__ void cpa_commit() {
    asm volatile("cp.async.commit_group;");
}
__device__ __forceinline__ void cpa_wait1() {
    asm volatile("cp.async.wait_group 1;" ::: "memory");
}
__device__ __forceinline__ void cpa_wait0() {
    asm volatile("cp.async.wait_group 0;" ::: "memory");
}
__device__ __forceinline__ void ldm4(uint32_t* r, uint32_t addr) {
    asm volatile("ldmatrix.sync.aligned.m8n8.x4.shared.b16 {%0,%1,%2,%3}, [%4];"
                 : "=r"(r[0]), "=r"(r[1]), "=r"(r[2]), "=r"(r[3]) : "r"(addr));
}
__device__ __forceinline__ void mma16816(float* d, const uint32_t* a, uint32_t b0, uint32_t b1) {
    asm volatile("mma.sync.aligned.m16n8k16.row.col.f32.bf16.bf16.f32 "
                 "{%0,%1,%2,%3}, {%4,%5,%6,%7}, {%8,%9}, {%0,%1,%2,%3};"
                 : "+f"(d[0]), "+f"(d[1]), "+f"(d[2]), "+f"(d[3])
                 : "r"(a[0]), "r"(a[1]), "r"(a[2]), "r"(a[3]), "r"(b0), "r"(b1));
}
__device__ __forceinline__ float tanh_fast(float x) {
    float e, r;
    asm("ex2.approx.f32 %0, %1;" : "=f"(e) : "f"(x * 2.88539008177792681f));
    asm("rcp.approx.f32 %0, %1;" : "=f"(r) : "f"(e + 1.0f));
    return fmaf(-2.0f, r, 1.0f);
}
__device__ __forceinline__ unsigned enc_f(float f) {
    unsigned u = __float_as_uint(f);
    return (u & 0x80000000u) ? ~u : (u | 0x80000000u);
}
__device__ __forceinline__ float dec_f(unsigned e) {
    unsigned u = (e & 0x80000000u) ? (e ^ 0x80000000u) : ~e;
    return __uint_as_float(u);
}

// ---------------------------------------------------------------------------
// K0: init
// ---------------------------------------------------------------------------
__global__ void k_init(float* __restrict__ out) {
    int i = blockIdx.x * blockDim.x + threadIdx.x;
    if (i < L) g_beta[i] = 0.0f;
    if (i < D) out[i] = 0.0f;
    if (i == 0) { g_maxbits = 0u; g_sumexp = 0.0f; }
}

// ---------------------------------------------------------------------------
// K1: c[a] = dot(W_att[a, D:2D], h_t) + b_att[a]
// ---------------------------------------------------------------------------
__global__ void k_ctx(const float* __restrict__ W, const float* __restrict__ ht,
                      const float* __restrict__ b) {
    int a = blockIdx.x;
    const float* w = W + (size_t)a * (2 * D) + D;
    float s = 0.0f;
    for (int k = threadIdx.x; k < D; k += 256) s = fmaf(w[k], ht[k], s);
    __shared__ float red[8];
    #pragma unroll
    for (int o = 16; o > 0; o >>= 1) s += __shfl_down_sync(0xffffffffu, s, o);
    if ((threadIdx.x & 31) == 0) red[threadIdx.x >> 5] = s;
    __syncthreads();
    if (threadIdx.x == 0) {
        float t = 0.0f;
        #pragma unroll
        for (int i = 0; i < 8; i++) t += red[i];
        g_c[a] = t + b[a];
    }
}

// ---------------------------------------------------------------------------
// K2a: h_i -> (hi, lo) bf16
// ---------------------------------------------------------------------------
__global__ void __launch_bounds__(256) k_conv_h(const float* __restrict__ h) {
    size_t i = ((size_t)blockIdx.x * 256 + threadIdx.x) * 4;
    float4 v = *(const float4*)(h + i);
    __nv_bfloat16 h0 = __float2bfloat16(v.x), h1 = __float2bfloat16(v.y);
    __nv_bfloat16 h2 = __float2bfloat16(v.z), h3 = __float2bfloat16(v.w);
    ushort4 hp, lp;
    hp.x = __bfloat16_as_ushort(h0); hp.y = __bfloat16_as_ushort(h1);
    hp.z = __bfloat16_as_ushort(h2); hp.w = __bfloat16_as_ushort(h3);
    lp.x = __bfloat16_as_ushort(__float2bfloat16(v.x - __bfloat162float(h0)));
    lp.y = __bfloat16_as_ushort(__float2bfloat16(v.y - __bfloat162float(h1)));
    lp.z = __bfloat16_as_ushort(__float2bfloat16(v.z - __bfloat162float(h2)));
    lp.w = __bfloat16_as_ushort(__float2bfloat16(v.w - __bfloat162float(h3)));
    *(ushort4*)(g_hA + i) = hp;
    *(ushort4*)(g_lA + i) = lp;
}

// ---------------------------------------------------------------------------
// K2b: W1 -> (hi, lo) bf16
// ---------------------------------------------------------------------------
__global__ void __launch_bounds__(256) k_conv_w(const float* __restrict__ W) {
    int idx = blockIdx.x * 256 + threadIdx.x;     // over A*D/4
    int a = idx >> 8, c = (idx & 255) * 4;
    float4 v = *(const float4*)(W + (size_t)a * (2 * D) + c);
    __nv_bfloat16 h0 = __float2bfloat16(v.x), h1 = __float2bfloat16(v.y);
    __nv_bfloat16 h2 = __float2bfloat16(v.z), h3 = __float2bfloat16(v.w);
    ushort4 hp, lp;
    hp.x = __bfloat16_as_ushort(h0); hp.y = __bfloat16_as_ushort(h1);
    hp.z = __bfloat16_as_ushort(h2); hp.w = __bfloat16_as_ushort(h3);
    lp.x = __bfloat16_as_ushort(__float2bfloat16(v.x - __bfloat162float(h0)));
    lp.y = __bfloat16_as_ushort(__float2bfloat16(v.y - __bfloat162float(h1)));
    lp.z = __bfloat16_as_ushort(__float2bfloat16(v.z - __bfloat162float(h2)));
    lp.w = __bfloat16_as_ushort(__float2bfloat16(v.w - __bfloat162float(h3)));
    size_t o = (size_t)a * D + c;
    *(ushort4*)(g_hB + o) = hp;
    *(ushort4*)(g_lB + o) = lp;
}

// ---------------------------------------------------------------------------
// K3: HMMA GEMM, cp.async 3-stage pipeline, XOR-swizzled 128B rows
// ---------------------------------------------------------------------------
struct LoadCtx {
    const char* srcA[2];   // hi, lo  (base of row block, element offset applied)
    const char* srcB[2];
    uint32_t dstoff;       // row*128 + swz_ch*16 for i=0
};

__global__ void __launch_bounds__(256, 1) k_gemm(const float* __restrict__ u_in) {
    extern __shared__ __align__(128) char smem[];
    const uint32_t sbase = smem_u32(smem);
    const int tid = threadIdx.x;
    const int lane = tid & 31, wid = tid >> 5;
    const int warp_m = wid >> 2, warp_n = wid & 3;
    const int l0 = blockIdx.x * BM, a0 = blockIdx.y * BN;

    // ---- cp.async mapping: thread t loads 4 chunks per tile, rows t>>3 + i*32
    const int crow = tid >> 3;                 // 0..31
    const int cch = tid & 7;                   // 16B chunk in row
    const uint32_t swz_ch = (uint32_t)(cch ^ (crow & 7));
    const uint32_t dbase = (uint32_t)crow * 128 + swz_ch * 16;
    const char* pAh = (const char*)(g_hA + ((size_t)(l0 + crow) * D + cch * 8));
    const char* pAl = (const char*)(g_lA + ((size_t)(l0 + crow) * D + cch * 8));
    const char* pBh = (const char*)(g_hB + ((size_t)(a0 + crow) * D + cch * 8));
    const char* pBl = (const char*)(g_lB + ((size_t)(a0 + crow) * D + cch * 8));
    const size_t gstep = (size_t)32 * D * 2;   // 32 rows in bytes

    // ---- ldmatrix addressing
    uint32_t aRow[4], aSw[4];
    #pragma unroll
    for (int i = 0; i < 4; i++) {
        int r = warp_m * 64 + i * 16 + (lane & 15);
        aRow[i] = (uint32_t)r * 128;
        aSw[i] = (uint32_t)(r & 7);
    }
    const uint32_t aCh = (uint32_t)(lane >> 4);      // 0/1
    uint32_t bRow[2], bSw[2];
    #pragma unroll
    for (int p = 0; p < 2; p++) {
        int r = warp_n * 32 + p * 16 + (lane & 7) + ((lane >> 4) & 1) * 8;
        bRow[p] = (uint32_t)r * 128;
        bSw[p] = (uint32_t)(r & 7);
    }
    const uint32_t bCh = (uint32_t)((lane >> 3) & 1); // 0/1

    float acc[4][4][4];
    #pragma unroll
    for (int i = 0; i < 4; i++)
        #pragma unroll
        for (int j = 0; j < 4; j++)
            #pragma unroll
            for (int r = 0; r < 4; r++) acc[i][j][r] = 0.0f;

    // ---- issue loads for a k-chunk into a stage
    auto issue = [&](int kc, int st) {
        const uint32_t sb = sbase + (uint32_t)st * STAGEB;
        const size_t ko = (size_t)kc * BK * 2;  // bytes into row
        #pragma unroll
        for (int i = 0; i < 4; i++) {
            const size_t go = ko + (size_t)i * gstep;
            const uint32_t doff = dbase + (uint32_t)i * 32 * 128;
            cpa16(sb + OFF_AH + doff, pAh + go);
            cpa16(sb + OFF_AL + doff, pAl + go);
            cpa16(sb + OFF_BH + doff, pBh + go);
            cpa16(sb + OFF_BL + doff, pBl + go);
        }
        cpa_commit();
    };

    issue(0, 0);
    issue(1, 1);

    for (int kc = 0; kc < NCH; kc++) {
        if (kc == NCH - 1) cpa_wait0(); else cpa_wait1();
        __syncthreads();
        if (kc + 2 < NCH) issue(kc + 2, (kc + 2) % STAGES);

        const uint32_t base = sbase + (uint32_t)(kc % STAGES) * STAGEB;
        #pragma unroll
        for (int ks = 0; ks < 4; ks++) {
            uint32_t ah[4][4], al[4][4], bh[2][4], bl[2][4];
            const uint32_t ac = (uint32_t)ks * 2 + aCh;
            const uint32_t bc = (uint32_t)ks * 2 + bCh;
            #pragma unroll
            for (int i = 0; i < 4; i++) {
                uint32_t ad = base + aRow[i] + ((ac ^ aSw[i]) << 4);
                ldm4(ah[i], ad + OFF_AH);
                ldm4(al[i], ad + OFF_AL);
            }
            #pragma unroll
            for (int p = 0; p < 2; p++) {
                uint32_t bd = base + bRow[p] + ((bc ^ bSw[p]) << 4);
                ldm4(bh[p], bd + OFF_BH);
                ldm4(bl[p], bd + OFF_BL);
            }
            #pragma unroll
            for (int i = 0; i < 4; i++)
                #pragma unroll
                for (int j = 0; j < 4; j++) {
                    const int p = j >> 1, q = (j & 1) * 2;
                    mma16816(acc[i][j], ah[i], bh[p][q], bh[p][q + 1]);
                    mma16816(acc[i][j], ah[i], bl[p][q], bl[p][q + 1]);
                    mma16816(acc[i][j], al[i], bh[p][q], bh[p][q + 1]);
                }
        }
        __syncthreads();
    }

    // ---- epilogue
    const int gID = lane >> 2, tig = lane & 3;
    float cl[4][2], ul[4][2];
    #pragma unroll
    for (int j = 0; j < 4; j++) {
        const int ag = a0 + warp_n * 32 + j * 8 + 2 * tig;
        cl[j][0] = g_c[ag];  cl[j][1] = g_c[ag + 1];
        ul[j][0] = u_in[ag]; ul[j][1] = u_in[ag + 1];
    }
    #pragma unroll
    for (int i = 0; i < 4; i++) {
        float sA = 0.0f, sB = 0.0f;
        #pragma unroll
        for (int j = 0; j < 4; j++) {
            sA = fmaf(tanh_fast(acc[i][j][0] + cl[j][0]), ul[j][0], sA);
            sA = fmaf(tanh_fast(acc[i][j][1] + cl[j][1]), ul[j][1], sA);
            sB = fmaf(tanh_fast(acc[i][j][2] + cl[j][0]), ul[j][0], sB);
            sB = fmaf(tanh_fast(acc[i][j][3] + cl[j][1]), ul[j][1], sB);
        }
        sA += __shfl_xor_sync(0xffffffffu, sA, 1);
        sA += __shfl_xor_sync(0xffffffffu, sA, 2);
        sB += __shfl_xor_sync(0xffffffffu, sB, 1);
        sB += __shfl_xor_sync(0xffffffffu, sB, 2);
        if (tig == 0) {
            const int r = l0 + warp_m * 64 + i * 16 + gID;
            atomicAdd(&g_beta[r], sA);
            atomicAdd(&g_beta[r + 8], sB);
        }
    }
}

// ---------------------------------------------------------------------------
// K4: softmax stats
// ---------------------------------------------------------------------------
__global__ void k_max() {
    int i = blockIdx.x * 1024 + threadIdx.x;
    float v = g_beta[i];
    #pragma unroll
    for (int o = 16; o > 0; o >>= 1) v = fmaxf(v, __shfl_xor_sync(0xffffffffu, v, o));
    __shared__ float r[32];
    if ((threadIdx.x & 31) == 0) r[threadIdx.x >> 5] = v;
    __syncthreads();
    if (threadIdx.x < 32) {
        v = r[threadIdx.x];
        #pragma unroll
        for (int o = 16; o > 0; o >>= 1) v = fmaxf(v, __shfl_xor_sync(0xffffffffu, v, o));
        if (threadIdx.x == 0) atomicMax(&g_maxbits, enc_f(v));
    }
}
__global__ void k_sum() {
    int i = blockIdx.x * 1024 + threadIdx.x;
    float mx = dec_f(g_maxbits);
    float v = expf(g_beta[i] - mx);
    #pragma unroll
    for (int o = 16; o > 0; o >>= 1) v += __shfl_xor_sync(0xffffffffu, v, o);
    __shared__ float r[32];
    if ((threadIdx.x & 31) == 0) r[threadIdx.x >> 5] = v;
    __syncthreads();
    if (threadIdx.x < 32) {
        v = r[threadIdx.x];
        #pragma unroll
        for (int o = 16; o > 0; o >>= 1) v += __shfl_xor_sync(0xffffffffu, v, o);
        if (threadIdx.x == 0) atomicAdd(&g_sumexp, v);
    }
}

// ---------------------------------------------------------------------------
// K5: s[d] = sum_l alpha_l * h_i[l][d]
// ---------------------------------------------------------------------------
#define OROWS 128
__global__ void __launch_bounds__(256) k_out(const float* __restrict__ h_i,
                                             float* __restrict__ out) {
    __shared__ float w[OROWS];
    int l0 = blockIdx.x * OROWS;
    int tid = threadIdx.x;
    float mx = dec_f(g_maxbits), se = g_sumexp;
    if (tid < OROWS) w[tid] = expf(g_beta[l0 + tid] - mx) / se;
    __syncthreads();
    float acc[4] = {0.0f, 0.0f, 0.0f, 0.0f};
    for (int l = 0; l < OROWS; l++) {
        float wl = w[l];
        const float* rp = h_i + (size_t)(l0 + l) * D;
        #pragma unroll
        for (int j = 0; j < 4; j++)
            acc[j] = fmaf(wl, rp[tid + j * 256], acc[j]);
    }
    #pragma unroll
    for (int j = 0; j < 4; j++) atomicAdd(&out[tid + j * 256], acc[j]);
}

// ---------------------------------------------------------------------------
extern "C" void kernel_launch(void* const* d_in, const int* in_sizes, int n_in,
                              void* d_out, int out_size) {
    const float* h_i = (const float*)d_in[0];
    const float* h_t = (const float*)d_in[1];
    const float* W   = (const float*)d_in[2];
    const float* b   = (const float*)d_in[3];
    const float* u   = (const float*)d_in[4];
    float* out = (float*)d_out;

    static bool attr_set = false;
    if (!attr_set) {
        cudaFuncSetAttribute(k_gemm, cudaFuncAttributeMaxDynamicSharedMemorySize, SMEM_TOTAL);
        attr_set = true;
    }

    k_init<<<64, 256>>>(out);
    k_ctx<<<ADIM, 256>>>(W, h_t, b);
    k_conv_h<<<(int)(((size_t)L * D) / 1024), 256>>>(h_i);
    k_conv_w<<<(ADIM * D) / 1024, 256>>>(W);
    dim3 g(L / BM, ADIM / BN);
    k_gemm<<<g, 256, SMEM_TOTAL>>>(u);
    k_max<<<16, 1024>>>();
    k_sum<<<16, 1024>>>();
    k_out<<<L / OROWS, 256>>>(h_i, out);
}